// round 1
// baseline (speedup 1.0000x reference)
#include <cuda_runtime.h>

#define NNODE 50000
#define NEDGE 800000
#define DIM   64
#define NREL  65
#define TILE  128
#define NTILES_MAX ((NEDGE + TILE - 1) / TILE + NREL)

// ---- scratch (static device globals; no allocation) ----
__device__ int   g_cnt[NNODE * NREL];     // (dst, rel) edge counts
__device__ int   g_relCnt[NREL];
__device__ int   g_relCur[NREL];
__device__ int   g_relOff[NREL + 1];      // edge offsets per relation (sorted order)
__device__ int   g_tileRel[NTILES_MAX];
__device__ int   g_tileStart[NTILES_MAX];
__device__ int   g_numTiles;
__device__ float g_norm[NEDGE];
__device__ int   g_perm[NEDGE];           // edge ids sorted by relation
__device__ float g_h[NNODE * DIM];        // layer-1 activations

// ---------------------------------------------------------------- zero
__global__ void k_zero() {
    int i = blockIdx.x * blockDim.x + threadIdx.x;
    if (i < NNODE * NREL / 4) {
        int4 z = make_int4(0, 0, 0, 0);
        ((int4*)g_cnt)[i] = z;
    }
    if (i < NREL) { g_relCnt[i] = 0; g_relCur[i] = 0; }
}

// ---------------------------------------------------------------- count
__global__ void k_count(const int* __restrict__ dst, const int* __restrict__ et) {
    int e = blockIdx.x * blockDim.x + threadIdx.x;
    if (e < NEDGE) {
        atomicAdd(&g_cnt[dst[e] * NREL + et[e]], 1);
        atomicAdd(&g_relCnt[et[e]], 1);
    }
}

// ---------------------------------------------------------------- scan + tile table
__global__ void k_scan() {
    __shared__ int sCnt[NREL];
    __shared__ int sTB[NREL];
    __shared__ int sEO[NREL];
    int tid = threadIdx.x;
    if (tid < NREL) sCnt[tid] = g_relCnt[tid];
    __syncthreads();
    if (tid == 0) {
        int eo = 0, to = 0;
        for (int r = 0; r < NREL; r++) {
            sEO[r] = eo; sTB[r] = to;
            g_relOff[r] = eo;
            eo += sCnt[r];
            to += (sCnt[r] + TILE - 1) / TILE;
        }
        g_relOff[NREL] = eo;
        g_numTiles = to;
    }
    __syncthreads();
    if (tid < NREL) {
        int c = sCnt[tid], nt = (c + TILE - 1) / TILE;
        int tb = sTB[tid], eo = sEO[tid];
        for (int i = 0; i < nt; i++) {
            g_tileRel[tb + i]   = tid;
            g_tileStart[tb + i] = eo + i * TILE;
        }
    }
}

// ---------------------------------------------------------------- norm + perm
__global__ void k_fill(const int* __restrict__ dst, const int* __restrict__ et) {
    int e = blockIdx.x * blockDim.x + threadIdx.x;
    if (e < NEDGE) {
        int r = et[e];
        int c = g_cnt[dst[e] * NREL + r];
        g_norm[e] = 1.0f / (float)max(c, 1);
        int pos = g_relOff[r] + atomicAdd(&g_relCur[r], 1);
        g_perm[pos] = e;
    }
}

// ---------------------------------------------------------------- self-loop GEMM: O = X @ Wl
__global__ void __launch_bounds__(256) k_selfloop(const float* __restrict__ X,
                                                  const float* __restrict__ Wl,
                                                  float* __restrict__ O) {
    extern __shared__ float sm[];
    float* Ws  = sm;           // 64*64
    float* XsT = sm + 4096;    // 64*TILE (transposed)
    int tid  = threadIdx.x;
    int base = blockIdx.x * TILE;

    const float4* Wr  = (const float4*)Wl;
    float4*       Ws4 = (float4*)Ws;
#pragma unroll
    for (int j = 0; j < 4; j++) Ws4[tid + j * 256] = Wr[tid + j * 256];

    int e = tid >> 1, half = tid & 1;
    int row = base + e;
    if (row < NNODE) {
        const float4* xr = (const float4*)(X + (long)row * DIM + half * 32);
#pragma unroll
        for (int j = 0; j < 8; j++) {
            float4 v = xr[j];
            int d = half * 32 + j * 4;
            XsT[(d + 0) * TILE + e] = v.x;
            XsT[(d + 1) * TILE + e] = v.y;
            XsT[(d + 2) * TILE + e] = v.z;
            XsT[(d + 3) * TILE + e] = v.w;
        }
    } else {
#pragma unroll
        for (int j = 0; j < 8; j++) {
            int d = half * 32 + j * 4;
            XsT[(d + 0) * TILE + e] = 0.f; XsT[(d + 1) * TILE + e] = 0.f;
            XsT[(d + 2) * TILE + e] = 0.f; XsT[(d + 3) * TILE + e] = 0.f;
        }
    }
    __syncthreads();

    int tx = tid & 15, ty = tid >> 4;
    float4 acc[8];
#pragma unroll
    for (int i = 0; i < 8; i++) acc[i] = make_float4(0.f, 0.f, 0.f, 0.f);
#pragma unroll 8
    for (int k = 0; k < DIM; k++) {
        float4 b  = *(const float4*)&Ws[k * DIM + tx * 4];
        float4 a0 = *(const float4*)&XsT[k * TILE + ty * 8];
        float4 a1 = *(const float4*)&XsT[k * TILE + ty * 8 + 4];
        float av[8] = {a0.x, a0.y, a0.z, a0.w, a1.x, a1.y, a1.z, a1.w};
#pragma unroll
        for (int i = 0; i < 8; i++) {
            acc[i].x += av[i] * b.x;
            acc[i].y += av[i] * b.y;
            acc[i].z += av[i] * b.z;
            acc[i].w += av[i] * b.w;
        }
    }
#pragma unroll
    for (int i = 0; i < 8; i++) {
        int row2 = base + ty * 8 + i;
        if (row2 < NNODE)
            *(float4*)&O[(long)row2 * DIM + tx * 4] = acc[i];
    }
}

// ---------------------------------------------------------------- edge gather-GEMM-scatter
__global__ void __launch_bounds__(256) k_edges(const float* __restrict__ X,
                                               const float* __restrict__ W,
                                               const int* __restrict__ src,
                                               const int* __restrict__ dst,
                                               float* __restrict__ O) {
    int t = blockIdx.x;
    if (t >= g_numTiles) return;
    int r  = g_tileRel[t];
    int s0 = g_tileStart[t];
    int m  = min(g_relOff[r + 1] - s0, TILE);

    extern __shared__ float sm[];
    float* Ws   = sm;                        // 64*64 = 16KB
    float* XsT  = sm + 4096;                 // 64*128 = 32KB (transposed, norm applied)
    int*   sDst = (int*)(sm + 4096 + 8192);  // 128 ints
    int tid = threadIdx.x;

    const float4* Wr  = (const float4*)(W + (long)r * DIM * DIM);
    float4*       Ws4 = (float4*)Ws;
#pragma unroll
    for (int j = 0; j < 4; j++) Ws4[tid + j * 256] = Wr[tid + j * 256];

    int e = tid >> 1, half = tid & 1;
    if (e < m) {
        int   edge = g_perm[s0 + e];
        int   sr   = src[edge];
        float nrm  = g_norm[edge];
        if (half == 0) sDst[e] = dst[edge];
        const float4* xr = (const float4*)(X + (long)sr * DIM + half * 32);
#pragma unroll
        for (int j = 0; j < 8; j++) {
            float4 v = xr[j];
            int d = half * 32 + j * 4;
            XsT[(d + 0) * TILE + e] = v.x * nrm;
            XsT[(d + 1) * TILE + e] = v.y * nrm;
            XsT[(d + 2) * TILE + e] = v.z * nrm;
            XsT[(d + 3) * TILE + e] = v.w * nrm;
        }
    } else {
#pragma unroll
        for (int j = 0; j < 8; j++) {
            int d = half * 32 + j * 4;
            XsT[(d + 0) * TILE + e] = 0.f; XsT[(d + 1) * TILE + e] = 0.f;
            XsT[(d + 2) * TILE + e] = 0.f; XsT[(d + 3) * TILE + e] = 0.f;
        }
    }
    __syncthreads();

    int tx = tid & 15, ty = tid >> 4;
    float4 acc[8];
#pragma unroll
    for (int i = 0; i < 8; i++) acc[i] = make_float4(0.f, 0.f, 0.f, 0.f);
#pragma unroll 8
    for (int k = 0; k < DIM; k++) {
        float4 b  = *(const float4*)&Ws[k * DIM + tx * 4];
        float4 a0 = *(const float4*)&XsT[k * TILE + ty * 8];
        float4 a1 = *(const float4*)&XsT[k * TILE + ty * 8 + 4];
        float av[8] = {a0.x, a0.y, a0.z, a0.w, a1.x, a1.y, a1.z, a1.w};
#pragma unroll
        for (int i = 0; i < 8; i++) {
            acc[i].x += av[i] * b.x;
            acc[i].y += av[i] * b.y;
            acc[i].z += av[i] * b.z;
            acc[i].w += av[i] * b.w;
        }
    }

#pragma unroll
    for (int i = 0; i < 8; i++) {
        int e2 = ty * 8 + i;
        if (e2 < m) {
            float* o = O + (long)sDst[e2] * DIM + tx * 4;
            asm volatile("red.global.add.v4.f32 [%0], {%1,%2,%3,%4};"
                         :: "l"(o), "f"(acc[i].x), "f"(acc[i].y),
                            "f"(acc[i].z), "f"(acc[i].w)
                         : "memory");
        }
    }
}

// ---------------------------------------------------------------- relu
__global__ void k_relu(float* __restrict__ O, int n4) {
    int i = blockIdx.x * blockDim.x + threadIdx.x;
    if (i < n4) {
        float4 v = ((float4*)O)[i];
        v.x = fmaxf(v.x, 0.f); v.y = fmaxf(v.y, 0.f);
        v.z = fmaxf(v.z, 0.f); v.w = fmaxf(v.w, 0.f);
        ((float4*)O)[i] = v;
    }
}

// ---------------------------------------------------------------- launch
extern "C" void kernel_launch(void* const* d_in, const int* in_sizes, int n_in,
                              void* d_out, int out_size) {
    const float* x   = (const float*)d_in[0];
    const int*   src = (const int*)d_in[1];
    const int*   dst = (const int*)d_in[2];
    const int*   et  = (const int*)d_in[3];
    const float* W1  = (const float*)d_in[4];
    const float* Wl1 = (const float*)d_in[5];
    const float* W2  = (const float*)d_in[6];
    const float* Wl2 = (const float*)d_in[7];
    float* out = (float*)d_out;

    void* hsym = nullptr;
    cudaGetSymbolAddress(&hsym, g_h);
    float* h = (float*)hsym;

    cudaFuncSetAttribute(k_edges,    cudaFuncAttributeMaxDynamicSharedMemorySize, 49664);
    cudaFuncSetAttribute(k_selfloop, cudaFuncAttributeMaxDynamicSharedMemorySize, 49152);

    const int TPB = 256;
    // preprocessing (shared by both layers)
    k_zero<<<(NNODE * NREL / 4 + TPB - 1) / TPB, TPB>>>();
    k_count<<<(NEDGE + TPB - 1) / TPB, TPB>>>(dst, et);
    k_scan<<<1, 128>>>();
    k_fill<<<(NEDGE + TPB - 1) / TPB, TPB>>>(dst, et);

    int nBlocksRows = (NNODE + TILE - 1) / TILE;
    int n4 = NNODE * DIM / 4;

    // layer 1: h = relu(edges(x,W1) + x@Wl1)
    k_selfloop<<<nBlocksRows, TPB, 49152>>>(x, Wl1, h);
    k_edges<<<NTILES_MAX, TPB, 49664>>>(x, W1, src, dst, h);
    k_relu<<<(n4 + TPB - 1) / TPB, TPB>>>(h, n4);

    // layer 2: out = relu(edges(h,W2) + h@Wl2)
    k_selfloop<<<nBlocksRows, TPB, 49152>>>(h, Wl2, out);
    k_edges<<<NTILES_MAX, TPB, 49664>>>(h, W2, src, dst, out);
    k_relu<<<(n4 + TPB - 1) / TPB, TPB>>>(out, n4);
}

// round 2
// speedup vs baseline: 1.9152x; 1.9152x over previous
#include <cuda_runtime.h>

#define NNODE 50000
#define NEDGE 800000
#define DIM   64
#define NREL  65
#define TILE  128
#define EPB   2048
#define NB    ((NEDGE + EPB - 1) / EPB)          // 391 hist/scatter blocks
#define NTILES_MAX ((NEDGE + TILE - 1) / TILE + NREL)

// ---- scratch (static device globals; no allocation) ----
__device__ int   g_cnt[NNODE * NREL];       // (dst, rel) edge counts
__device__ int   g_blockHist[NB * NREL];    // per-block relation histogram -> prefix
__device__ int   g_relCnt[NREL];
__device__ int   g_relOff[NREL + 1];
__device__ int   g_tileRel[NTILES_MAX];
__device__ int   g_tileStart[NTILES_MAX];
__device__ int   g_numTiles;
__device__ int   g_srcP[NEDGE];             // src, sorted by relation
__device__ int   g_dstP[NEDGE];             // dst, sorted by relation
__device__ float g_normP[NEDGE];            // 1/cnt, sorted by relation
__device__ float g_h[NNODE * DIM];          // layer-1 activations

// ---------------------------------------------------------------- zero g_cnt
__global__ void k_zero() {
    int i = blockIdx.x * blockDim.x + threadIdx.x;
    if (i < NNODE * NREL / 4) {
        int4 z = make_int4(0, 0, 0, 0);
        ((int4*)g_cnt)[i] = z;
    }
}

// ---------------------------------------------------------------- per-block histogram + (dst,rel) counts
__global__ void __launch_bounds__(256) k_hist(const int* __restrict__ dst,
                                              const int* __restrict__ et) {
    __shared__ int h[NREL];
    int tid = threadIdx.x, b = blockIdx.x;
    if (tid < NREL) h[tid] = 0;
    __syncthreads();
    int s = b * EPB, e_end = min(s + EPB, NEDGE);
    for (int e = s + tid; e < e_end; e += 256) {
        int r = et[e];
        atomicAdd(&h[r], 1);
        atomicAdd(&g_cnt[dst[e] * NREL + r], 1);   // spread: 3.25M addresses
    }
    __syncthreads();
    if (tid < NREL) g_blockHist[b * NREL + tid] = h[tid];
}

// ---------------------------------------------------------------- per-relation scan over blocks
__global__ void k_scanRel() {
    __shared__ int v[NB];
    int r = blockIdx.x, tid = threadIdx.x;
    for (int b = tid; b < NB; b += blockDim.x) v[b] = g_blockHist[b * NREL + r];
    __syncthreads();
    if (tid == 0) {
        int acc = 0;
        for (int b = 0; b < NB; b++) { int t = v[b]; v[b] = acc; acc += t; }
        g_relCnt[r] = acc;
    }
    __syncthreads();
    for (int b = tid; b < NB; b += blockDim.x) g_blockHist[b * NREL + r] = v[b];
}

// ---------------------------------------------------------------- relation offsets + tile table
__global__ void k_scan() {
    __shared__ int sCnt[NREL];
    __shared__ int sTB[NREL];
    __shared__ int sEO[NREL];
    int tid = threadIdx.x;
    if (tid < NREL) sCnt[tid] = g_relCnt[tid];
    __syncthreads();
    if (tid == 0) {
        int eo = 0, to = 0;
        for (int r = 0; r < NREL; r++) {
            sEO[r] = eo; sTB[r] = to;
            g_relOff[r] = eo;
            eo += sCnt[r];
            to += (sCnt[r] + TILE - 1) / TILE;
        }
        g_relOff[NREL] = eo;
        g_numTiles = to;
    }
    __syncthreads();
    if (tid < NREL) {
        int c = sCnt[tid], nt = (c + TILE - 1) / TILE;
        int tb = sTB[tid], eo = sEO[tid];
        for (int i = 0; i < nt; i++) {
            g_tileRel[tb + i]   = tid;
            g_tileStart[tb + i] = eo + i * TILE;
        }
    }
}

// ---------------------------------------------------------------- scatter into sorted arrays
__global__ void __launch_bounds__(256) k_scatter(const int* __restrict__ src,
                                                 const int* __restrict__ dst,
                                                 const int* __restrict__ et) {
    __shared__ int cur[NREL];
    int tid = threadIdx.x, b = blockIdx.x;
    if (tid < NREL) cur[tid] = g_relOff[tid] + g_blockHist[b * NREL + tid];
    __syncthreads();
    int s = b * EPB, e_end = min(s + EPB, NEDGE);
    for (int e = s + tid; e < e_end; e += 256) {
        int r = et[e], d = dst[e];
        int pos = atomicAdd(&cur[r], 1);           // shared-mem rank, no L2 contention
        g_srcP[pos]  = src[e];
        g_dstP[pos]  = d;
        g_normP[pos] = 1.0f / (float)max(g_cnt[d * NREL + r], 1);
    }
}

// ---------------------------------------------------------------- self-loop GEMM: O = X @ Wl
__global__ void __launch_bounds__(256) k_selfloop(const float* __restrict__ X,
                                                  const float* __restrict__ Wl,
                                                  float* __restrict__ O) {
    extern __shared__ float sm[];
    float* Ws  = sm;           // 64*64
    float* XsT = sm + 4096;    // 64*TILE (transposed)
    int tid  = threadIdx.x;
    int base = blockIdx.x * TILE;

    const float4* Wr  = (const float4*)Wl;
    float4*       Ws4 = (float4*)Ws;
#pragma unroll
    for (int j = 0; j < 4; j++) Ws4[tid + j * 256] = Wr[tid + j * 256];

    int e = tid >> 1, half = tid & 1;
    int row = base + e;
    if (row < NNODE) {
        const float4* xr = (const float4*)(X + (long)row * DIM + half * 32);
#pragma unroll
        for (int j = 0; j < 8; j++) {
            float4 v = xr[j];
            int d = half * 32 + j * 4;
            XsT[(d + 0) * TILE + e] = v.x;
            XsT[(d + 1) * TILE + e] = v.y;
            XsT[(d + 2) * TILE + e] = v.z;
            XsT[(d + 3) * TILE + e] = v.w;
        }
    } else {
#pragma unroll
        for (int j = 0; j < 8; j++) {
            int d = half * 32 + j * 4;
            XsT[(d + 0) * TILE + e] = 0.f; XsT[(d + 1) * TILE + e] = 0.f;
            XsT[(d + 2) * TILE + e] = 0.f; XsT[(d + 3) * TILE + e] = 0.f;
        }
    }
    __syncthreads();

    int tx = tid & 15, ty = tid >> 4;
    float4 acc[8];
#pragma unroll
    for (int i = 0; i < 8; i++) acc[i] = make_float4(0.f, 0.f, 0.f, 0.f);
#pragma unroll 8
    for (int k = 0; k < DIM; k++) {
        float4 b  = *(const float4*)&Ws[k * DIM + tx * 4];
        float4 a0 = *(const float4*)&XsT[k * TILE + ty * 8];
        float4 a1 = *(const float4*)&XsT[k * TILE + ty * 8 + 4];
        float av[8] = {a0.x, a0.y, a0.z, a0.w, a1.x, a1.y, a1.z, a1.w};
#pragma unroll
        for (int i = 0; i < 8; i++) {
            acc[i].x += av[i] * b.x;
            acc[i].y += av[i] * b.y;
            acc[i].z += av[i] * b.z;
            acc[i].w += av[i] * b.w;
        }
    }
#pragma unroll
    for (int i = 0; i < 8; i++) {
        int row2 = base + ty * 8 + i;
        if (row2 < NNODE)
            *(float4*)&O[(long)row2 * DIM + tx * 4] = acc[i];
    }
}

// ---------------------------------------------------------------- edge gather-GEMM-scatter
__global__ void __launch_bounds__(256) k_edges(const float* __restrict__ X,
                                               const float* __restrict__ W,
                                               float* __restrict__ O) {
    int t = blockIdx.x;
    if (t >= g_numTiles) return;
    int r  = g_tileRel[t];
    int s0 = g_tileStart[t];
    int m  = min(g_relOff[r + 1] - s0, TILE);

    extern __shared__ float sm[];
    float* Ws   = sm;                        // 64*64 = 16KB
    float* XsT  = sm + 4096;                 // 64*128 = 32KB (transposed, norm applied)
    int*   sDst = (int*)(sm + 4096 + 8192);  // 128 ints
    int tid = threadIdx.x;

    const float4* Wr  = (const float4*)(W + (long)r * DIM * DIM);
    float4*       Ws4 = (float4*)Ws;
#pragma unroll
    for (int j = 0; j < 4; j++) Ws4[tid + j * 256] = Wr[tid + j * 256];

    int e = tid >> 1, half = tid & 1;
    if (e < m) {
        int   sr  = g_srcP[s0 + e];
        float nrm = g_normP[s0 + e];
        if (half == 0) sDst[e] = g_dstP[s0 + e];
        const float4* xr = (const float4*)(X + (long)sr * DIM + half * 32);
#pragma unroll
        for (int j = 0; j < 8; j++) {
            float4 v = xr[j];
            int d = half * 32 + j * 4;
            XsT[(d + 0) * TILE + e] = v.x * nrm;
            XsT[(d + 1) * TILE + e] = v.y * nrm;
            XsT[(d + 2) * TILE + e] = v.z * nrm;
            XsT[(d + 3) * TILE + e] = v.w * nrm;
        }
    } else {
#pragma unroll
        for (int j = 0; j < 8; j++) {
            int d = half * 32 + j * 4;
            XsT[(d + 0) * TILE + e] = 0.f; XsT[(d + 1) * TILE + e] = 0.f;
            XsT[(d + 2) * TILE + e] = 0.f; XsT[(d + 3) * TILE + e] = 0.f;
        }
    }
    __syncthreads();

    int tx = tid & 15, ty = tid >> 4;
    float4 acc[8];
#pragma unroll
    for (int i = 0; i < 8; i++) acc[i] = make_float4(0.f, 0.f, 0.f, 0.f);
#pragma unroll 8
    for (int k = 0; k < DIM; k++) {
        float4 b  = *(const float4*)&Ws[k * DIM + tx * 4];
        float4 a0 = *(const float4*)&XsT[k * TILE + ty * 8];
        float4 a1 = *(const float4*)&XsT[k * TILE + ty * 8 + 4];
        float av[8] = {a0.x, a0.y, a0.z, a0.w, a1.x, a1.y, a1.z, a1.w};
#pragma unroll
        for (int i = 0; i < 8; i++) {
            acc[i].x += av[i] * b.x;
            acc[i].y += av[i] * b.y;
            acc[i].z += av[i] * b.z;
            acc[i].w += av[i] * b.w;
        }
    }

#pragma unroll
    for (int i = 0; i < 8; i++) {
        int e2 = ty * 8 + i;
        if (e2 < m) {
            float* o = O + (long)sDst[e2] * DIM + tx * 4;
            asm volatile("red.global.add.v4.f32 [%0], {%1,%2,%3,%4};"
                         :: "l"(o), "f"(acc[i].x), "f"(acc[i].y),
                            "f"(acc[i].z), "f"(acc[i].w)
                         : "memory");
        }
    }
}

// ---------------------------------------------------------------- relu
__global__ void k_relu(float* __restrict__ O, int n4) {
    int i = blockIdx.x * blockDim.x + threadIdx.x;
    if (i < n4) {
        float4 v = ((float4*)O)[i];
        v.x = fmaxf(v.x, 0.f); v.y = fmaxf(v.y, 0.f);
        v.z = fmaxf(v.z, 0.f); v.w = fmaxf(v.w, 0.f);
        ((float4*)O)[i] = v;
    }
}

// ---------------------------------------------------------------- launch
extern "C" void kernel_launch(void* const* d_in, const int* in_sizes, int n_in,
                              void* d_out, int out_size) {
    const float* x   = (const float*)d_in[0];
    const int*   src = (const int*)d_in[1];
    const int*   dst = (const int*)d_in[2];
    const int*   et  = (const int*)d_in[3];
    const float* W1  = (const float*)d_in[4];
    const float* Wl1 = (const float*)d_in[5];
    const float* W2  = (const float*)d_in[6];
    const float* Wl2 = (const float*)d_in[7];
    float* out = (float*)d_out;

    void* hsym = nullptr;
    cudaGetSymbolAddress(&hsym, g_h);
    float* h = (float*)hsym;

    cudaFuncSetAttribute(k_edges,    cudaFuncAttributeMaxDynamicSharedMemorySize, 49664);
    cudaFuncSetAttribute(k_selfloop, cudaFuncAttributeMaxDynamicSharedMemorySize, 49152);

    const int TPB = 256;
    // preprocessing: contention-free counting sort by relation
    k_zero<<<(NNODE * NREL / 4 + TPB - 1) / TPB, TPB>>>();
    k_hist<<<NB, TPB>>>(dst, et);
    k_scanRel<<<NREL, 256>>>();
    k_scan<<<1, 128>>>();
    k_scatter<<<NB, TPB>>>(src, dst, et);

    int nBlocksRows = (NNODE + TILE - 1) / TILE;
    int n4 = NNODE * DIM / 4;

    // layer 1: h = relu(edges(x,W1) + x@Wl1)
    k_selfloop<<<nBlocksRows, TPB, 49152>>>(x, Wl1, h);
    k_edges<<<NTILES_MAX, TPB, 49664>>>(x, W1, h);
    k_relu<<<(n4 + TPB - 1) / TPB, TPB>>>(h, n4);

    // layer 2: out = relu(edges(h,W2) + h@Wl2)
    k_selfloop<<<nBlocksRows, TPB, 49152>>>(h, Wl2, out);
    k_edges<<<NTILES_MAX, TPB, 49664>>>(h, W2, out);
    k_relu<<<(n4 + TPB - 1) / TPB, TPB>>>(out, n4);
}